// round 7
// baseline (speedup 1.0000x reference)
#include <cuda_runtime.h>
#include <cstdint>

#define B_ 32
#define N_ 6000
#define M_ 128
#define L_ 81
#define BN (B_*N_)

// ---------------- Threefry-2x32 (bit-exact JAX replica) ----------------
struct U2 { unsigned a, b; };

__host__ __device__ constexpr unsigned rotl32(unsigned x, int d) {
    return (x << d) | (x >> (32 - d));
}

__host__ __device__ constexpr U2 threefry2x32(unsigned k0, unsigned k1,
                                              unsigned x0, unsigned x1) {
    unsigned ks0 = k0, ks1 = k1, ks2 = k0 ^ k1 ^ 0x1BD11BDAu;
    x0 += ks0; x1 += ks1;
#define TF_RND(r) { x0 += x1; x1 = rotl32(x1, r); x1 ^= x0; }
    TF_RND(13) TF_RND(15) TF_RND(26) TF_RND(6)
    x0 += ks1; x1 += ks2 + 1u;
    TF_RND(17) TF_RND(29) TF_RND(16) TF_RND(24)
    x0 += ks2; x1 += ks0 + 2u;
    TF_RND(13) TF_RND(15) TF_RND(26) TF_RND(6)
    x0 += ks0; x1 += ks1 + 3u;
    TF_RND(17) TF_RND(29) TF_RND(16) TF_RND(24)
    x0 += ks1; x1 += ks2 + 4u;
    TF_RND(13) TF_RND(15) TF_RND(26) TF_RND(6)
    x0 += ks2; x1 += ks0 + 5u;
#undef TF_RND
    return U2{x0, x1};
}

// ---- JAX threefry_partitionable=True semantics (verified passing) ----
constexpr U2 KP = threefry2x32(0u, 42u, 0u, 0u);
constexpr U2 KN = threefry2x32(0u, 42u, 0u, 1u);
constexpr U2 PH = threefry2x32(KP.a, KP.b, 0u, 0u);
constexpr U2 PL = threefry2x32(KP.a, KP.b, 0u, 1u);
constexpr U2 NH = threefry2x32(KN.a, KN.b, 0u, 0u);
constexpr U2 NL = threefry2x32(KN.a, KN.b, 0u, 1u);

constexpr unsigned SPAN_P = 1279u;
constexpr unsigned SPAN_N = 3839u;
__host__ __device__ constexpr unsigned mult_of(unsigned span) {
    unsigned m = 65536u % span;
    return (m * m) % span;
}
constexpr unsigned MUL_P = mult_of(SPAN_P);
constexpr unsigned MUL_N = mult_of(SPAN_N);

// ---------------- scratch ----------------
__device__ int g_max_idx[BN];
__device__ int g_pos_s[BN];
__device__ int g_neg_s[BN];
__device__ unsigned g_list[B_ * (128 + 384)];
__device__ int g_count;

// ---------------- kernel 1: IoU max/argmax + threefry scores ----------------
__global__ void iou_kernel(const float* __restrict__ roi,
                           const float* __restrict__ gt) {
    int b = blockIdx.y;
    int n = blockIdx.x * blockDim.x + threadIdx.x;
    __shared__ float4 sgt[M_];
    if (threadIdx.x < M_)
        sgt[threadIdx.x] = reinterpret_cast<const float4*>(gt)[b * M_ + threadIdx.x];
    if (blockIdx.x == 0 && blockIdx.y == 0 && threadIdx.x == 0) g_count = 0;
    __syncthreads();
    if (n >= N_) return;

    int j = b * N_ + n;
    float4 r = reinterpret_cast<const float4*>(roi)[j];
    float by1 = r.x, bx1 = r.y, by2 = r.z, bx2 = r.w;
    float area = __fmul_rn(__fsub_rn(by2, by1), __fsub_rn(bx2, bx1));
    float best = -1.0f;
    int bi = 0;
#pragma unroll 4
    for (int m = 0; m < M_; m++) {
        float4 g = sgt[m];
        float xt = fmaxf(bx1, g.y);
        float yt = fmaxf(by1, g.x);
        float xb = fminf(bx2, g.w);
        float yb = fminf(by2, g.z);
        float iw = fmaxf(__fsub_rn(xb, xt), 0.0f);
        float ih = fmaxf(__fsub_rn(yb, yt), 0.0f);
        float inter = __fmul_rn(iw, ih);
        // reference bug: gt_area == 0 -> union = bbox_area - inter
        float iou = __fdiv_rn(inter, __fsub_rn(area, inter));
        if (iou > best) { best = iou; bi = m; }
    }
    g_max_idx[j] = bi;

    unsigned uj = (unsigned)j;
    U2 ph = threefry2x32(PH.a, PH.b, 0u, uj);
    U2 pl = threefry2x32(PL.a, PL.b, 0u, uj);
    U2 nh = threefry2x32(NH.a, NH.b, 0u, uj);
    U2 nl = threefry2x32(NL.a, NL.b, 0u, uj);
    unsigned p_hi = ph.a ^ ph.b, p_lo = pl.a ^ pl.b;
    unsigned n_hi = nh.a ^ nh.b, n_lo = nl.a ^ nl.b;
    unsigned rp = 1u + ((p_hi % SPAN_P) * MUL_P + (p_lo % SPAN_P)) % SPAN_P;
    unsigned rn = 1u + ((n_hi % SPAN_N) * MUL_N + (n_lo % SPAN_N)) % SPAN_N;

    g_pos_s[j] = (best > 0.5f) ? (int)rp : 0;
    g_neg_s[j] = (best < 0.5f && best > 0.1f) ? (int)rn : 0;
}

// ---------------- kernel 2: exact stable top-count selection ----------------
__global__ void select_kernel() {
    int b = blockIdx.x >> 1;
    int kind = blockIdx.x & 1;            // 0 = pos, 1 = neg
    int span = kind ? (int)SPAN_N : (int)SPAN_P;
    int target = kind ? 384 : 128;
    const int* row = (kind ? g_neg_s : g_pos_s) + b * N_;

    __shared__ int hist[3840];
    __shared__ int chunk[256];
    __shared__ int sh_T, sh_quota, sh_run;
    __shared__ int warp_tot[8];
    int tid = threadIdx.x;

    for (int v = tid; v <= span; v += blockDim.x) hist[v] = 0;
    if (tid == 0) { sh_T = 0; sh_quota = 0; sh_run = 0; }
    __syncthreads();
    for (int n = tid; n < N_; n += blockDim.x) {
        int v = row[n];
        if (v > 0) atomicAdd(&hist[v], 1);
    }
    __syncthreads();

    const int CH = 16;
    {
        int vhi = span - tid * CH;
        int s = 0;
#pragma unroll
        for (int k = 0; k < CH; k++) {
            int v = vhi - k;
            if (v >= 1) s += hist[v];
        }
        chunk[tid] = s;
    }
    __syncthreads();
#pragma unroll
    for (int off = 1; off < 256; off <<= 1) {
        int x = (tid >= off) ? chunk[tid - off] : 0;
        __syncthreads();
        chunk[tid] += x;
        __syncthreads();
    }
    {
        int incl = chunk[tid];
        int excl = (tid > 0) ? chunk[tid - 1] : 0;
        if (excl < target && incl >= target) {
            int c = excl;
            int vhi = span - tid * CH;
            for (int k = 0; k < CH; k++) {
                int v = vhi - k;
                if (v < 1) break;
                c += hist[v];
                if (c >= target) {
                    sh_T = v;
                    sh_quota = target - (c - hist[v]);
                    break;
                }
            }
        }
    }
    __syncthreads();
    int T = sh_T, quota = sh_quota;
    int lane = tid & 31, w = tid >> 5;

    for (int base = 0; base < N_; base += blockDim.x) {
        int n = base + tid;
        int v = (n < N_) ? row[n] : 0;
        bool eq = (T > 0) && (v == T);
        unsigned bal = __ballot_sync(0xffffffffu, eq);
        if (lane == 0) warp_tot[w] = __popc(bal);
        __syncthreads();
        int wbase = 0;
        for (int k = 0; k < w; k++) wbase += warp_tot[k];
        int excl = sh_run + wbase + __popc(bal & ((1u << lane) - 1u));
        bool sel = (n < N_) && (v > T || (eq && excl < quota));
        if (sel) {
            int j = b * N_ + n;
            unsigned gi = (unsigned)g_max_idx[j];
            unsigned pk = (unsigned)n | ((unsigned)b << 13) | (gi << 18)
                        | ((unsigned)(kind == 0) << 25);
            int p = atomicAdd(&g_count, 1);
            g_list[p] = pk;
        }
        __syncthreads();
        if (tid == 0) {
            int tot = 0;
            for (int k = 0; k < 8; k++) tot += warp_tot[k];
            sh_run += tot;
        }
        __syncthreads();
    }
}

// ---------------- kernel 3: sparse scatter of selected entries ----------------
__global__ void scatter_kernel(const float* __restrict__ roi,
                               const float* __restrict__ gt,
                               const int* __restrict__ gt_labels,
                               float* __restrict__ out) {
    int i = blockIdx.x * blockDim.x + threadIdx.x;
    if (i >= g_count) return;
    unsigned pk = g_list[i];
    int n = pk & 0x1FFF;
    int b = (pk >> 13) & 31;
    int gi = (pk >> 18) & 127;
    int isPos = (pk >> 25) & 1;
    int base = b * N_ + n;
    int label = isPos ? gt_labels[b * M_ + gi] : 0;

    float* labels_out = out + (size_t)BN * L_ * 4;
    labels_out[(size_t)base * L_ + label] = 1.0f;

    if (isPos) {
        float4 r = reinterpret_cast<const float4*>(roi)[base];
        float4 g = reinterpret_cast<const float4*>(gt)[b * M_ + gi];
        float bw = r.w - r.y;
        float bh = r.z - r.x;
        float bcx = r.y + 0.5f * bw;
        float bcy = r.x + 0.5f * bh;
        float gw = g.w - g.y;
        float gh = g.z - g.x;
        float gcx = g.y + 0.5f * gw;
        float gcy = g.x + 0.5f * gh;
        bw = (bw == 0.f) ? 1e-3f : bw;
        bh = (bh == 0.f) ? 1e-3f : bh;
        float dx = (gw == 0.f) ? 0.f : (gcx - bcx) / bw;
        float dy = (gh == 0.f) ? 0.f : (gcy - bcy) / bh;
        float dw = (gw == 0.f) ? 0.f : logf(gw / bw);
        float dh = (gh == 0.f) ? 0.f : logf(gh / bh);
        reinterpret_cast<float4*>(out)[(size_t)base * L_ + label] =
            make_float4(dy, dx, dh, dw);
    }
}

extern "C" void kernel_launch(void* const* d_in, const int* in_sizes, int n_in,
                              void* d_out, int out_size) {
    const float* roi = (const float*)d_in[0];       // [32,6000,4] f32
    const float* gt  = (const float*)d_in[1];       // [32,128,4]  f32
    const int*   gl  = (const int*)d_in[2];         // [32,128]    i32
    float* out = (float*)d_out;

    static cudaStream_t s_side = nullptr;
    static cudaEvent_t ev_fork = nullptr, ev_join = nullptr;
    if (s_side == nullptr) {
        cudaStreamCreateWithFlags(&s_side, cudaStreamNonBlocking);
        cudaEventCreateWithFlags(&ev_fork, cudaEventDisableTiming);
        cudaEventCreateWithFlags(&ev_join, cudaEventDisableTiming);
    }

    // Fork: branch A = driver-tuned memset (graph memset node),
    //       branch B = iou -> select.
    cudaEventRecord(ev_fork, 0);
    cudaStreamWaitEvent(s_side, ev_fork, 0);
    cudaMemsetAsync(out, 0, (size_t)out_size * sizeof(float), s_side);

    dim3 g1((N_ + 255) / 256, B_);
    iou_kernel<<<g1, 256>>>(roi, gt);
    select_kernel<<<64, 256>>>();

    // Join, then scatter (needs zeroed buffer + selection list).
    cudaEventRecord(ev_join, s_side);
    cudaStreamWaitEvent(0, ev_join, 0);
    scatter_kernel<<<64, 256>>>(roi, gt, gl, out);
}

// round 9
// speedup vs baseline: 2.1195x; 2.1195x over previous
#include <cuda_runtime.h>
#include <cstdint>

#define B_ 32
#define N_ 6000
#define M_ 128
#define L_ 81
#define BN (B_*N_)

// ---------------- Threefry-2x32 (bit-exact JAX replica) ----------------
struct U2 { unsigned a, b; };

__host__ __device__ constexpr unsigned rotl32(unsigned x, int d) {
    return (x << d) | (x >> (32 - d));
}

__host__ __device__ constexpr U2 threefry2x32(unsigned k0, unsigned k1,
                                              unsigned x0, unsigned x1) {
    unsigned ks0 = k0, ks1 = k1, ks2 = k0 ^ k1 ^ 0x1BD11BDAu;
    x0 += ks0; x1 += ks1;
#define TF_RND(r) { x0 += x1; x1 = rotl32(x1, r); x1 ^= x0; }
    TF_RND(13) TF_RND(15) TF_RND(26) TF_RND(6)
    x0 += ks1; x1 += ks2 + 1u;
    TF_RND(17) TF_RND(29) TF_RND(16) TF_RND(24)
    x0 += ks2; x1 += ks0 + 2u;
    TF_RND(13) TF_RND(15) TF_RND(26) TF_RND(6)
    x0 += ks0; x1 += ks1 + 3u;
    TF_RND(17) TF_RND(29) TF_RND(16) TF_RND(24)
    x0 += ks1; x1 += ks2 + 4u;
    TF_RND(13) TF_RND(15) TF_RND(26) TF_RND(6)
    x0 += ks2; x1 += ks0 + 5u;
#undef TF_RND
    return U2{x0, x1};
}

// ---- JAX threefry_partitionable=True semantics (verified passing) ----
constexpr U2 KP = threefry2x32(0u, 42u, 0u, 0u);
constexpr U2 KN = threefry2x32(0u, 42u, 0u, 1u);
constexpr U2 PH = threefry2x32(KP.a, KP.b, 0u, 0u);
constexpr U2 PL = threefry2x32(KP.a, KP.b, 0u, 1u);
constexpr U2 NH = threefry2x32(KN.a, KN.b, 0u, 0u);
constexpr U2 NL = threefry2x32(KN.a, KN.b, 0u, 1u);

constexpr unsigned SPAN_P = 1279u;
constexpr unsigned SPAN_N = 3839u;
__host__ __device__ constexpr unsigned mult_of(unsigned span) {
    unsigned m = 65536u % span;
    return (m * m) % span;
}
constexpr unsigned MUL_P = mult_of(SPAN_P);
constexpr unsigned MUL_N = mult_of(SPAN_N);

// ---------------- scratch ----------------
__device__ int g_max_idx[BN];
__device__ int g_pos_s[BN];
__device__ int g_neg_s[BN];
__device__ unsigned g_list[B_ * (128 + 384)];
__device__ int g_count;

// ---------------- kernel 1: IoU max/argmax + threefry scores ----------------
// Division-free fast path: iou = fdiv_rn(x, fsub_rn(area, x)) is monotone
// non-decreasing in x (correctly-rounded ops), so max iou == iou(max inter)
// exactly. Argmax index can differ from the reference only if the top-2
// distinct inters are within ~2.4e-7 relative (quotients could round equal);
// detect that band and fall back to the exact per-m division loop (rare).
__global__ void iou_kernel(const float* __restrict__ roi,
                           const float* __restrict__ gt) {
    int b = blockIdx.y;
    int n = blockIdx.x * blockDim.x + threadIdx.x;
    __shared__ float4 sgt[M_];
    if (threadIdx.x < M_)
        sgt[threadIdx.x] = reinterpret_cast<const float4*>(gt)[b * M_ + threadIdx.x];
    if (blockIdx.x == 0 && blockIdx.y == 0 && threadIdx.x == 0) g_count = 0;
    __syncthreads();
    if (n >= N_) return;

    int j = b * N_ + n;
    float4 r = reinterpret_cast<const float4*>(roi)[j];
    float by1 = r.x, bx1 = r.y, by2 = r.z, bx2 = r.w;
    float area = __fmul_rn(__fsub_rn(by2, by1), __fsub_rn(bx2, bx1));

    float v1 = -1.0f, v2 = -1.0f;   // top-2 inter values (v1 first-max)
    int bi = 0;
#pragma unroll 4
    for (int m = 0; m < M_; m++) {
        float4 g = sgt[m];
        float xt = fmaxf(bx1, g.y);
        float yt = fmaxf(by1, g.x);
        float xb = fminf(bx2, g.w);
        float yb = fminf(by2, g.z);
        float iw = fmaxf(__fsub_rn(xb, xt), 0.0f);
        float ih = fmaxf(__fsub_rn(yb, yt), 0.0f);
        float inter = __fmul_rn(iw, ih);
        if (inter > v1) { v2 = v1; v1 = inter; bi = m; }
        else if (inter > v2 && inter < v1) { v2 = inter; }
    }
    // reference bug: gt_area == 0 -> union = bbox_area - inter
    float best = __fdiv_rn(v1, __fsub_rn(area, v1));

    // Exact-argmax fixup when top-2 inters are suspiciously close (rare).
    if (v2 >= 0.0f && v2 < v1 && v2 >= __fmul_rn(v1, 0.9999997f)) {
        float bb = -1.0f; bi = 0;
        for (int m = 0; m < M_; m++) {
            float4 g = sgt[m];
            float xt = fmaxf(bx1, g.y);
            float yt = fmaxf(by1, g.x);
            float xb = fminf(bx2, g.w);
            float yb = fminf(by2, g.z);
            float iw = fmaxf(__fsub_rn(xb, xt), 0.0f);
            float ih = fmaxf(__fsub_rn(yb, yt), 0.0f);
            float inter = __fmul_rn(iw, ih);
            float iou = __fdiv_rn(inter, __fsub_rn(area, inter));
            if (iou > bb) { bb = iou; bi = m; }
        }
        best = bb;
    }
    g_max_idx[j] = bi;

    unsigned uj = (unsigned)j;
    U2 ph = threefry2x32(PH.a, PH.b, 0u, uj);
    U2 pl = threefry2x32(PL.a, PL.b, 0u, uj);
    U2 nh = threefry2x32(NH.a, NH.b, 0u, uj);
    U2 nl = threefry2x32(NL.a, NL.b, 0u, uj);
    unsigned p_hi = ph.a ^ ph.b, p_lo = pl.a ^ pl.b;
    unsigned n_hi = nh.a ^ nh.b, n_lo = nl.a ^ nl.b;
    unsigned rp = 1u + ((p_hi % SPAN_P) * MUL_P + (p_lo % SPAN_P)) % SPAN_P;
    unsigned rn = 1u + ((n_hi % SPAN_N) * MUL_N + (n_lo % SPAN_N)) % SPAN_N;

    g_pos_s[j] = (best > 0.5f) ? (int)rp : 0;
    g_neg_s[j] = (best < 0.5f && best > 0.1f) ? (int)rn : 0;
}

// ---------------- kernel 2: exact stable top-count selection ----------------
#define SEL_BD 512
#define SEL_CH 8
__global__ void select_kernel() {
    int b = blockIdx.x >> 1;
    int kind = blockIdx.x & 1;            // 0 = pos, 1 = neg
    int span = kind ? (int)SPAN_N : (int)SPAN_P;
    int target = kind ? 384 : 128;
    const int* row = (kind ? g_neg_s : g_pos_s) + b * N_;

    __shared__ int hist[3840];
    __shared__ int chunk[SEL_BD];
    __shared__ int sh_T, sh_quota, sh_run;
    __shared__ int warp_tot[SEL_BD / 32];
    int tid = threadIdx.x;

    for (int v = tid; v <= span; v += SEL_BD) hist[v] = 0;
    if (tid == 0) { sh_T = 0; sh_quota = 0; sh_run = 0; }
    __syncthreads();
    for (int n = tid; n < N_; n += SEL_BD) {
        int v = row[n];
        if (v > 0) atomicAdd(&hist[v], 1);
    }
    __syncthreads();

    {
        int vhi = span - tid * SEL_CH;
        int s = 0;
#pragma unroll
        for (int k = 0; k < SEL_CH; k++) {
            int v = vhi - k;
            if (v >= 1) s += hist[v];
        }
        chunk[tid] = s;
    }
    __syncthreads();
#pragma unroll
    for (int off = 1; off < SEL_BD; off <<= 1) {
        int x = (tid >= off) ? chunk[tid - off] : 0;
        __syncthreads();
        chunk[tid] += x;
        __syncthreads();
    }
    {
        int incl = chunk[tid];
        int excl = (tid > 0) ? chunk[tid - 1] : 0;
        if (excl < target && incl >= target) {
            int c = excl;
            int vhi = span - tid * SEL_CH;
            for (int k = 0; k < SEL_CH; k++) {
                int v = vhi - k;
                if (v < 1) break;
                c += hist[v];
                if (c >= target) {
                    sh_T = v;
                    sh_quota = target - (c - hist[v]);
                    break;
                }
            }
        }
    }
    __syncthreads();
    int T = sh_T, quota = sh_quota;
    int lane = tid & 31, w = tid >> 5;

    for (int base = 0; base < N_; base += SEL_BD) {
        int n = base + tid;
        int v = (n < N_) ? row[n] : 0;
        bool eq = (T > 0) && (v == T);
        unsigned bal = __ballot_sync(0xffffffffu, eq);
        if (lane == 0) warp_tot[w] = __popc(bal);
        __syncthreads();
        int wbase = 0;
        for (int k = 0; k < w; k++) wbase += warp_tot[k];
        int excl = sh_run + wbase + __popc(bal & ((1u << lane) - 1u));
        bool sel = (n < N_) && (v > T || (eq && excl < quota));
        if (sel) {
            int j = b * N_ + n;
            unsigned gi = (unsigned)g_max_idx[j];
            unsigned pk = (unsigned)n | ((unsigned)b << 13) | (gi << 18)
                        | ((unsigned)(kind == 0) << 25);
            int p = atomicAdd(&g_count, 1);
            g_list[p] = pk;
        }
        __syncthreads();
        if (tid == 0) {
            int tot = 0;
            for (int k = 0; k < SEL_BD / 32; k++) tot += warp_tot[k];
            sh_run += tot;
        }
        __syncthreads();
    }
}

// ---------------- kernel 3: TMA bulk-store zero-fill ----------------
// Fill 16KB of SMEM zeros once per block, then stream cp.async.bulk
// SMEM -> GMEM chunks. Bypasses the L1TEX/STG store path entirely.
#define ZCHUNK 16384
__global__ void zero_tma_kernel(char* __restrict__ out, unsigned long long total) {
    __shared__ __align__(128) char zbuf[ZCHUNK];
    for (int i = threadIdx.x * 16; i < ZCHUNK; i += blockDim.x * 16)
        *reinterpret_cast<float4*>(zbuf + i) = make_float4(0.f, 0.f, 0.f, 0.f);
    __syncthreads();
    asm volatile("fence.proxy.async.shared::cta;" ::: "memory");

    if (threadIdx.x == 0) {
        uint32_t saddr;
        asm("{ .reg .u64 t; cvta.to.shared.u64 t, %1; cvt.u32.u64 %0, t; }"
            : "=r"(saddr) : "l"(zbuf));
        unsigned long long nchunks = total / ZCHUNK;
        for (unsigned long long c = blockIdx.x; c < nchunks; c += gridDim.x) {
            asm volatile(
                "cp.async.bulk.global.shared::cta.bulk_group [%0], [%1], %2;"
                :: "l"(out + c * (unsigned long long)ZCHUNK), "r"(saddr),
                   "r"(ZCHUNK) : "memory");
        }
        if (blockIdx.x == 0) {
            unsigned long long done = nchunks * (unsigned long long)ZCHUNK;
            unsigned tail = (unsigned)(total - done);   // multiple of 16
            if (tail)
                asm volatile(
                    "cp.async.bulk.global.shared::cta.bulk_group [%0], [%1], %2;"
                    :: "l"(out + done), "r"(saddr), "r"(tail) : "memory");
        }
        asm volatile("cp.async.bulk.commit_group;" ::: "memory");
        asm volatile("cp.async.bulk.wait_group 0;" ::: "memory");
    }
}

// ---------------- kernel 4: sparse scatter of selected entries ----------------
__global__ void scatter_kernel(const float* __restrict__ roi,
                               const float* __restrict__ gt,
                               const int* __restrict__ gt_labels,
                               float* __restrict__ out) {
    int i = blockIdx.x * blockDim.x + threadIdx.x;
    if (i >= g_count) return;
    unsigned pk = g_list[i];
    int n = pk & 0x1FFF;
    int b = (pk >> 13) & 31;
    int gi = (pk >> 18) & 127;
    int isPos = (pk >> 25) & 1;
    int base = b * N_ + n;
    int label = isPos ? gt_labels[b * M_ + gi] : 0;

    float* labels_out = out + (size_t)BN * L_ * 4;
    labels_out[(size_t)base * L_ + label] = 1.0f;

    if (isPos) {
        float4 r = reinterpret_cast<const float4*>(roi)[base];
        float4 g = reinterpret_cast<const float4*>(gt)[b * M_ + gi];
        float bw = r.w - r.y;
        float bh = r.z - r.x;
        float bcx = r.y + 0.5f * bw;
        float bcy = r.x + 0.5f * bh;
        float gw = g.w - g.y;
        float gh = g.z - g.x;
        float gcx = g.y + 0.5f * gw;
        float gcy = g.x + 0.5f * gh;
        bw = (bw == 0.f) ? 1e-3f : bw;
        bh = (bh == 0.f) ? 1e-3f : bh;
        float dx = (gw == 0.f) ? 0.f : (gcx - bcx) / bw;
        float dy = (gh == 0.f) ? 0.f : (gcy - bcy) / bh;
        float dw = (gw == 0.f) ? 0.f : logf(gw / bw);
        float dh = (gh == 0.f) ? 0.f : logf(gh / bh);
        reinterpret_cast<float4*>(out)[(size_t)base * L_ + label] =
            make_float4(dy, dx, dh, dw);
    }
}

extern "C" void kernel_launch(void* const* d_in, const int* in_sizes, int n_in,
                              void* d_out, int out_size) {
    const float* roi = (const float*)d_in[0];       // [32,6000,4] f32
    const float* gt  = (const float*)d_in[1];       // [32,128,4]  f32
    const int*   gl  = (const int*)d_in[2];         // [32,128]    i32
    float* out = (float*)d_out;

    static cudaStream_t s_side = nullptr;
    static cudaEvent_t ev_fork = nullptr, ev_join = nullptr;
    if (s_side == nullptr) {
        cudaStreamCreateWithFlags(&s_side, cudaStreamNonBlocking);
        cudaEventCreateWithFlags(&ev_fork, cudaEventDisableTiming);
        cudaEventCreateWithFlags(&ev_join, cudaEventDisableTiming);
    }

    unsigned long long total = (unsigned long long)out_size * 4ull;  // bytes

    // Fork: branch A = TMA bulk-store zero-fill, branch B = iou -> select.
    cudaEventRecord(ev_fork, 0);
    cudaStreamWaitEvent(s_side, ev_fork, 0);
    zero_tma_kernel<<<592, 128, 0, s_side>>>((char*)out, total);

    dim3 g1((N_ + 255) / 256, B_);
    iou_kernel<<<g1, 256>>>(roi, gt);
    select_kernel<<<64, SEL_BD>>>();

    // Join, then scatter (needs zeroed buffer + selection list).
    cudaEventRecord(ev_join, s_side);
    cudaStreamWaitEvent(0, ev_join, 0);
    scatter_kernel<<<64, 256>>>(roi, gt, gl, out);
}